// round 2
// baseline (speedup 1.0000x reference)
#include <cuda_runtime.h>
#include <math.h>

#define B_   16
#define C_   256
#define HW_  1024      // H*W tokens per batch
#define HEADS_ 4
#define DH_  64
#define GROUPS_ 32
#define CPG_ 8         // channels per group
#define EPS_ 1e-6f
#define RS2_ 0.70710678118654752440f
#define QSCALE_ (1.0f/16.0f)   // 1/sqrt(C)

// ---------------- scratch (device globals; no allocation allowed) ----------
__device__ float g_xn[B_*HW_*C_];   // normalized x, (B,N,C)
__device__ float g_q [B_*HW_*C_];
__device__ float g_k [B_*HW_*C_];
__device__ float g_v [B_*HW_*C_];
__device__ float g_h [B_*HW_*C_];   // attention output, (B,N,C)

// ---------------- Kernel 1: GroupNorm + transpose to (B,N,C) ---------------
__global__ __launch_bounds__(256) void gn_kernel(
    const float* __restrict__ x, const float* __restrict__ sc,
    const float* __restrict__ bi)
{
    __shared__ float xs[CPG_*HW_];       // 8192 floats = 32 KB
    __shared__ float red[64];
    int b = blockIdx.x >> 5;
    int g = blockIdx.x & 31;
    const float* base = x + (size_t)b*C_*HW_ + (size_t)g*CPG_*HW_;
    int tid = threadIdx.x;

    float s = 0.f, sq = 0.f;
    #pragma unroll 8
    for (int i = tid; i < CPG_*HW_; i += 256) {
        float v = base[i];
        xs[i] = v;
        s += v; sq += v*v;
    }
    #pragma unroll
    for (int o = 16; o; o >>= 1) {
        s  += __shfl_xor_sync(0xffffffffu, s,  o);
        sq += __shfl_xor_sync(0xffffffffu, sq, o);
    }
    int w = tid >> 5;
    if ((tid & 31) == 0) { red[w] = s; red[32 + w] = sq; }
    __syncthreads();
    if (tid < 32) {
        s  = (tid < 8) ? red[tid]      : 0.f;
        sq = (tid < 8) ? red[32 + tid] : 0.f;
        #pragma unroll
        for (int o = 4; o; o >>= 1) {
            s  += __shfl_xor_sync(0xffffffffu, s,  o);
            sq += __shfl_xor_sync(0xffffffffu, sq, o);
        }
        if (tid == 0) { red[0] = s; red[1] = sq; }
    }
    __syncthreads();
    float mean = red[0] * (1.f / 8192.f);
    float var  = red[1] * (1.f / 8192.f) - mean*mean;
    float rinv = rsqrtf(var + EPS_);

    float scs[CPG_], bis[CPG_];
    #pragma unroll
    for (int c = 0; c < CPG_; c++) { scs[c] = sc[g*CPG_+c]; bis[c] = bi[g*CPG_+c]; }

    for (int n = tid; n < HW_; n += 256) {
        float buf[CPG_];
        #pragma unroll
        for (int c = 0; c < CPG_; c++)
            buf[c] = (xs[c*HW_ + n] - mean) * rinv * scs[c] + bis[c];
        float4* dst = (float4*)&g_xn[((size_t)(b*HW_ + n))*C_ + g*CPG_];
        dst[0] = make_float4(buf[0], buf[1], buf[2], buf[3]);
        dst[1] = make_float4(buf[4], buf[5], buf[6], buf[7]);
    }
}

// ---------------- Kernel 2: fused QKV GEMM  (B*N,256)x(256,256) x3 ---------
__global__ __launch_bounds__(256) void qkv_kernel(
    const float* __restrict__ Wq, const float* __restrict__ bq,
    const float* __restrict__ Wk, const float* __restrict__ bk,
    const float* __restrict__ Wv, const float* __restrict__ bv)
{
    __shared__ float As[16][68];        // k-major, padded
    __shared__ float Bs[3][16][64];
    int m0 = blockIdx.y * 64;
    int d0 = blockIdx.x * 64;
    int tid = threadIdx.x;
    int ty = tid >> 4, tx = tid & 15;

    float accq[4][4] = {}, acck[4][4] = {}, accv[4][4] = {};

    for (int k0 = 0; k0 < C_; k0 += 16) {
        {   // A tile: 64 rows x 16 k, transposed into smem
            int row = tid >> 2, c4 = (tid & 3) * 4;
            float4 a = *(const float4*)&g_xn[(size_t)(m0 + row)*C_ + k0 + c4];
            As[c4+0][row] = a.x; As[c4+1][row] = a.y;
            As[c4+2][row] = a.z; As[c4+3][row] = a.w;
        }
        {   // W tiles: 16 rows x 64 cols each
            int row = tid >> 4, c4 = (tid & 15) * 4;
            size_t off = (size_t)(k0 + row)*C_ + d0 + c4;
            *(float4*)&Bs[0][row][c4] = *(const float4*)&Wq[off];
            *(float4*)&Bs[1][row][c4] = *(const float4*)&Wk[off];
            *(float4*)&Bs[2][row][c4] = *(const float4*)&Wv[off];
        }
        __syncthreads();
        #pragma unroll
        for (int kk = 0; kk < 16; kk++) {
            float4 a4 = *(const float4*)&As[kk][ty*4];
            float av[4] = {a4.x, a4.y, a4.z, a4.w};
            float4 q4 = *(const float4*)&Bs[0][kk][tx*4];
            float4 k4 = *(const float4*)&Bs[1][kk][tx*4];
            float4 v4 = *(const float4*)&Bs[2][kk][tx*4];
            float qv[4] = {q4.x,q4.y,q4.z,q4.w};
            float kv[4] = {k4.x,k4.y,k4.z,k4.w};
            float vv[4] = {v4.x,v4.y,v4.z,v4.w};
            #pragma unroll
            for (int a = 0; a < 4; a++)
                #pragma unroll
                for (int j = 0; j < 4; j++) {
                    accq[a][j] += av[a]*qv[j];
                    acck[a][j] += av[a]*kv[j];
                    accv[a][j] += av[a]*vv[j];
                }
        }
        __syncthreads();
    }
    float4 bq4 = *(const float4*)&bq[d0 + tx*4];
    float4 bk4 = *(const float4*)&bk[d0 + tx*4];
    float4 bv4 = *(const float4*)&bv[d0 + tx*4];
    #pragma unroll
    for (int a = 0; a < 4; a++) {
        size_t off = (size_t)(m0 + ty*4 + a)*C_ + d0 + tx*4;
        *(float4*)&g_q[off] = make_float4(accq[a][0]+bq4.x, accq[a][1]+bq4.y,
                                          accq[a][2]+bq4.z, accq[a][3]+bq4.w);
        *(float4*)&g_k[off] = make_float4(acck[a][0]+bk4.x, acck[a][1]+bk4.y,
                                          acck[a][2]+bk4.z, acck[a][3]+bk4.w);
        *(float4*)&g_v[off] = make_float4(accv[a][0]+bv4.x, accv[a][1]+bv4.y,
                                          accv[a][2]+bv4.z, accv[a][3]+bv4.w);
    }
}

// ---------------- Kernel 3: flash attention per (b,h), qtile=64 ------------
__global__ __launch_bounds__(256) void attn_kernel()
{
    extern __shared__ float sm[];
    float* Qs = sm;                // [64][68] d-major: Qs[d*68 + i]
    float* Ks = sm + 4352;         // [64][68] d-major
    float* Ps = sm + 8704;         // [64][68] j-major: Ps[j*68 + i]
    float* Vs = sm + 13056;        // [64][64] j-major

    int q0 = blockIdx.x * 64;
    int b  = blockIdx.y >> 2;
    int h  = blockIdx.y & 3;
    int tid = threadIdx.x;
    int ty = tid >> 4, tx = tid & 15;
    const size_t bbase = (size_t)b*HW_*C_ + (size_t)h*DH_;

    {   // load full 64x64 Q tile, transposed + pre-scaled (4 float4 per thread)
        int row = tid >> 2;
        #pragma unroll
        for (int cc = 0; cc < 4; cc++) {
            int c4 = (tid & 3) * 4 + cc * 16;
            float4 a = *(const float4*)&g_q[bbase + (size_t)(q0 + row)*C_ + c4];
            Qs[(c4+0)*68+row] = a.x*QSCALE_; Qs[(c4+1)*68+row] = a.y*QSCALE_;
            Qs[(c4+2)*68+row] = a.z*QSCALE_; Qs[(c4+3)*68+row] = a.w*QSCALE_;
        }
    }

    float m[4], l[4], o[4][4];
    #pragma unroll
    for (int a = 0; a < 4; a++) {
        m[a] = -1e30f; l[a] = 0.f;
        #pragma unroll
        for (int j = 0; j < 4; j++) o[a][j] = 0.f;
    }

    for (int kt = 0; kt < 16; kt++) {
        int row = tid >> 2;
        float4 kk4[4], vv4[4];
        #pragma unroll
        for (int cc = 0; cc < 4; cc++) {
            int c4 = (tid & 3) * 4 + cc * 16;
            kk4[cc] = *(const float4*)&g_k[bbase + (size_t)(kt*64 + row)*C_ + c4];
            vv4[cc] = *(const float4*)&g_v[bbase + (size_t)(kt*64 + row)*C_ + c4];
        }
        __syncthreads();   // previous PV done (and Q visible on first iter)
        #pragma unroll
        for (int cc = 0; cc < 4; cc++) {
            int c4 = (tid & 3) * 4 + cc * 16;
            Ks[(c4+0)*68+row] = kk4[cc].x; Ks[(c4+1)*68+row] = kk4[cc].y;
            Ks[(c4+2)*68+row] = kk4[cc].z; Ks[(c4+3)*68+row] = kk4[cc].w;
            *(float4*)&Vs[row*64 + c4] = vv4[cc];
        }
        __syncthreads();

        float s4[4][4] = {};
        #pragma unroll 8
        for (int d = 0; d < 64; d++) {
            float4 a4 = *(const float4*)&Qs[d*68 + ty*4];
            float4 b4 = *(const float4*)&Ks[d*68 + tx*4];
            float av[4] = {a4.x,a4.y,a4.z,a4.w};
            float bv[4] = {b4.x,b4.y,b4.z,b4.w};
            #pragma unroll
            for (int a = 0; a < 4; a++)
                #pragma unroll
                for (int j = 0; j < 4; j++)
                    s4[a][j] += av[a]*bv[j];
        }

        // online softmax row update (rows spread over ty, cols over 16 tx lanes)
        #pragma unroll
        for (int a = 0; a < 4; a++) {
            float tm = fmaxf(fmaxf(s4[a][0], s4[a][1]), fmaxf(s4[a][2], s4[a][3]));
            #pragma unroll
            for (int off = 1; off < 16; off <<= 1)
                tm = fmaxf(tm, __shfl_xor_sync(0xffffffffu, tm, off));
            float mn = fmaxf(m[a], tm);
            float corr = __expf(m[a] - mn);
            m[a] = mn;
            l[a] *= corr;
            #pragma unroll
            for (int j = 0; j < 4; j++) o[a][j] *= corr;
            float ls = 0.f;
            #pragma unroll
            for (int j = 0; j < 4; j++) {
                float p = __expf(s4[a][j] - mn);
                s4[a][j] = p;
                ls += p;
            }
            #pragma unroll
            for (int off = 1; off < 16; off <<= 1)
                ls += __shfl_xor_sync(0xffffffffu, ls, off);
            l[a] += ls;
        }
        // store P j-major (float4 over the 4 rows)
        #pragma unroll
        for (int j = 0; j < 4; j++)
            *(float4*)&Ps[(tx*4+j)*68 + ty*4] =
                make_float4(s4[0][j], s4[1][j], s4[2][j], s4[3][j]);
        __syncthreads();

        #pragma unroll 8
        for (int jj = 0; jj < 64; jj++) {
            float4 a4 = *(const float4*)&Ps[jj*68 + ty*4];
            float4 b4 = *(const float4*)&Vs[jj*64 + tx*4];
            float av[4] = {a4.x,a4.y,a4.z,a4.w};
            float bv[4] = {b4.x,b4.y,b4.z,b4.w};
            #pragma unroll
            for (int a = 0; a < 4; a++)
                #pragma unroll
                for (int j = 0; j < 4; j++)
                    o[a][j] += av[a]*bv[j];
        }
    }

    #pragma unroll
    for (int a = 0; a < 4; a++) {
        float rl = 1.f / l[a];
        *(float4*)&g_h[bbase + (size_t)(q0 + ty*4 + a)*C_ + tx*4] =
            make_float4(o[a][0]*rl, o[a][1]*rl, o[a][2]*rl, o[a][3]*rl);
    }
}

// ---------------- Kernel 4: proj GEMM + bias + residual + 1/sqrt(2) --------
__global__ __launch_bounds__(256) void proj_kernel(
    const float* __restrict__ Wp, const float* __restrict__ bp,
    const float* __restrict__ x, float* __restrict__ out)
{
    __shared__ float As[16][68];
    __shared__ float Bs[16][64];
    int m0 = blockIdx.y * 64;
    int d0 = blockIdx.x * 64;
    int tid = threadIdx.x;
    int ty = tid >> 4, tx = tid & 15;

    float acc[4][4] = {};

    for (int k0 = 0; k0 < C_; k0 += 16) {
        {
            int row = tid >> 2, c4 = (tid & 3) * 4;
            float4 a = *(const float4*)&g_h[(size_t)(m0 + row)*C_ + k0 + c4];
            As[c4+0][row] = a.x; As[c4+1][row] = a.y;
            As[c4+2][row] = a.z; As[c4+3][row] = a.w;
        }
        {
            int row = tid >> 4, c4 = (tid & 15) * 4;
            *(float4*)&Bs[row][c4] = *(const float4*)&Wp[(size_t)(k0 + row)*C_ + d0 + c4];
        }
        __syncthreads();
        #pragma unroll
        for (int kk = 0; kk < 16; kk++) {
            float4 a4 = *(const float4*)&As[kk][ty*4];
            float4 b4 = *(const float4*)&Bs[kk][tx*4];
            float av[4] = {a4.x,a4.y,a4.z,a4.w};
            float bv[4] = {b4.x,b4.y,b4.z,b4.w};
            #pragma unroll
            for (int a = 0; a < 4; a++)
                #pragma unroll
                for (int j = 0; j < 4; j++)
                    acc[a][j] += av[a]*bv[j];
        }
        __syncthreads();
    }

    // output layout (B,C,H,W): out[b, d, n]; tile is 64 tokens of one batch
    int btok = m0 / HW_;
    int n0   = m0 % HW_;
    #pragma unroll
    for (int j = 0; j < 4; j++) {
        int d = d0 + tx*4 + j;
        size_t idx = (size_t)btok*C_*HW_ + (size_t)d*HW_ + n0 + ty*4;
        float4 xv = *(const float4*)&x[idx];
        float bpv = bp[d];
        *(float4*)&out[idx] = make_float4(
            (acc[0][j] + bpv + xv.x) * RS2_,
            (acc[1][j] + bpv + xv.y) * RS2_,
            (acc[2][j] + bpv + xv.z) * RS2_,
            (acc[3][j] + bpv + xv.w) * RS2_);
    }
}

// ---------------------------------------------------------------------------
extern "C" void kernel_launch(void* const* d_in, const int* in_sizes, int n_in,
                              void* d_out, int out_size)
{
    const float* x   = (const float*)d_in[0];
    const float* gns = (const float*)d_in[1];
    const float* gnb = (const float*)d_in[2];
    const float* Wq  = (const float*)d_in[3];
    const float* bq  = (const float*)d_in[4];
    const float* Wk  = (const float*)d_in[5];
    const float* bk  = (const float*)d_in[6];
    const float* Wv  = (const float*)d_in[7];
    const float* bv  = (const float*)d_in[8];
    const float* Wp  = (const float*)d_in[9];
    const float* bp  = (const float*)d_in[10];
    float* out = (float*)d_out;

    cudaFuncSetAttribute(attn_kernel,
                         cudaFuncAttributeMaxDynamicSharedMemorySize, 70000);

    gn_kernel<<<B_*GROUPS_, 256>>>(x, gns, gnb);
    qkv_kernel<<<dim3(C_/64, B_*HW_/64), 256>>>(Wq, bq, Wk, bk, Wv, bv);
    attn_kernel<<<dim3(HW_/64, B_*HEADS_), 256, 17152*sizeof(float)>>>();
    proj_kernel<<<dim3(C_/64, B_*HW_/64), 256>>>(Wp, bp, x, out);
}

// round 4
// speedup vs baseline: 2.2905x; 2.2905x over previous
#include <cuda_runtime.h>
#include <cstdint>
#include <math.h>

#define B_   16
#define C_   256
#define HW_  1024
#define HEADS_ 4
#define DH_  64
#define GROUPS_ 32
#define CPG_ 8
#define EPS_ 1e-6f
#define RS2_ 0.70710678118654752440f
#define QSCALE_ (1.0f/16.0f)

// ---------------- scratch ----------------
__device__ float g_xn[B_*HW_*C_];   // GN output, (B,N,C), tf32-rounded
__device__ float g_q [B_*HW_*C_];   // tf32-rounded, pre-scaled by 1/16
__device__ float g_k [B_*HW_*C_];
__device__ float g_v [B_*HW_*C_];
__device__ float g_h [B_*HW_*C_];   // attention out, tf32-rounded

// ---------------- helpers ----------------
__device__ __forceinline__ float f2t(float x){
    uint32_t u; asm("cvt.rna.tf32.f32 %0, %1;" : "=r"(u) : "f"(x));
    return __uint_as_float(u);
}
// D += A(16x8,row) * B(8x8,col)  tf32, fp32 accum
__device__ __forceinline__ void mma8(float* c, float a0, float a1, float a2, float a3,
                                     float b0, float b1){
    asm volatile("mma.sync.aligned.m16n8k8.row.col.f32.tf32.tf32.f32 "
        "{%0,%1,%2,%3}, {%4,%5,%6,%7}, {%8,%9}, {%0,%1,%2,%3};"
        : "+f"(c[0]), "+f"(c[1]), "+f"(c[2]), "+f"(c[3])
        : "r"(__float_as_uint(a0)), "r"(__float_as_uint(a1)),
          "r"(__float_as_uint(a2)), "r"(__float_as_uint(a3)),
          "r"(__float_as_uint(b0)), "r"(__float_as_uint(b1)));
}

// ---------------- Kernel 1: GroupNorm -> (B,N,C) tf32 ----------------
__global__ __launch_bounds__(256) void gn_kernel(
    const float* __restrict__ x, const float* __restrict__ sc,
    const float* __restrict__ bi)
{
    __shared__ float xs[CPG_*HW_];
    __shared__ float red[64];
    int b = blockIdx.x >> 5, g = blockIdx.x & 31;
    const float* base = x + (size_t)b*C_*HW_ + (size_t)g*CPG_*HW_;
    int tid = threadIdx.x;
    float s = 0.f, sq = 0.f;
    #pragma unroll 8
    for (int i = tid; i < CPG_*HW_; i += 256) {
        float v = base[i]; xs[i] = v; s += v; sq += v*v;
    }
    #pragma unroll
    for (int o = 16; o; o >>= 1) {
        s  += __shfl_xor_sync(0xffffffffu, s,  o);
        sq += __shfl_xor_sync(0xffffffffu, sq, o);
    }
    int w = tid >> 5;
    if ((tid & 31) == 0) { red[w] = s; red[32+w] = sq; }
    __syncthreads();
    if (tid < 32) {
        s  = (tid < 8) ? red[tid]    : 0.f;
        sq = (tid < 8) ? red[32+tid] : 0.f;
        #pragma unroll
        for (int o = 4; o; o >>= 1) {
            s  += __shfl_xor_sync(0xffffffffu, s,  o);
            sq += __shfl_xor_sync(0xffffffffu, sq, o);
        }
        if (tid == 0) { red[0] = s; red[1] = sq; }
    }
    __syncthreads();
    float mean = red[0] * (1.f/8192.f);
    float var  = red[1] * (1.f/8192.f) - mean*mean;
    float rinv = rsqrtf(var + EPS_);
    float scs[CPG_], bis[CPG_];
    #pragma unroll
    for (int c = 0; c < CPG_; c++) { scs[c] = sc[g*CPG_+c]; bis[c] = bi[g*CPG_+c]; }
    for (int n = tid; n < HW_; n += 256) {
        float buf[CPG_];
        #pragma unroll
        for (int c = 0; c < CPG_; c++)
            buf[c] = f2t((xs[c*HW_+n] - mean)*rinv*scs[c] + bis[c]);
        float4* dst = (float4*)&g_xn[((size_t)(b*HW_+n))*C_ + g*CPG_];
        dst[0] = make_float4(buf[0],buf[1],buf[2],buf[3]);
        dst[1] = make_float4(buf[4],buf[5],buf[6],buf[7]);
    }
}

// ---------------- Kernel 2: fused QKV, tf32 mma.sync ----------------
#define SA 36
#define SB 72
__global__ __launch_bounds__(256) void qkv_kernel(
    const float* __restrict__ Wq, const float* __restrict__ bq,
    const float* __restrict__ Wk, const float* __restrict__ bk,
    const float* __restrict__ Wv, const float* __restrict__ bv)
{
    extern __shared__ float sm[];
    float* sA  = sm;                    // 128 x SA
    float* sB0 = sm  + 128*SA;          // 32 x SB each
    float* sB1 = sB0 + 32*SB;
    float* sB2 = sB1 + 32*SB;
    int d0 = blockIdx.x*64, m0 = blockIdx.y*128;
    int tid = threadIdx.x, wid = tid>>5, lane = tid&31;
    int g = lane>>2, t = lane&3;
    int m0w = (wid>>1)*32, n0w = (wid&1)*32;

    float acc[3][2][4][4];
    #pragma unroll
    for (int z = 0; z < 3; z++)
        #pragma unroll
        for (int mt = 0; mt < 2; mt++)
            #pragma unroll
            for (int nt = 0; nt < 4; nt++)
                #pragma unroll
                for (int i = 0; i < 4; i++) acc[z][mt][nt][i] = 0.f;

    for (int kc = 0; kc < 8; kc++) {
        int k0 = kc*32;
        __syncthreads();
        for (int f = tid; f < 1024; f += 256) {           // A: 128x32
            int row = f>>3, c4 = (f&7)*4;
            *(float4*)&sA[row*SA + c4] =
                *(const float4*)&g_xn[(size_t)(m0+row)*C_ + k0 + c4];
        }
        for (int f = tid; f < 512; f += 256) {            // B: 32x64 x3 (tf32)
            int row = f>>4, c4 = (f&15)*4;
            size_t off = (size_t)(k0+row)*C_ + d0 + c4;
            float4 w;
            w = *(const float4*)&Wq[off];
            w.x=f2t(w.x); w.y=f2t(w.y); w.z=f2t(w.z); w.w=f2t(w.w);
            *(float4*)&sB0[row*SB + c4] = w;
            w = *(const float4*)&Wk[off];
            w.x=f2t(w.x); w.y=f2t(w.y); w.z=f2t(w.z); w.w=f2t(w.w);
            *(float4*)&sB1[row*SB + c4] = w;
            w = *(const float4*)&Wv[off];
            w.x=f2t(w.x); w.y=f2t(w.y); w.z=f2t(w.z); w.w=f2t(w.w);
            *(float4*)&sB2[row*SB + c4] = w;
        }
        __syncthreads();
        #pragma unroll
        for (int s = 0; s < 4; s++) {
            int k8 = s*8;
            float a[2][4];
            #pragma unroll
            for (int mt = 0; mt < 2; mt++) {
                int r = m0w + mt*16 + g;
                a[mt][0] = sA[r*SA + k8 + t];
                a[mt][1] = sA[(r+8)*SA + k8 + t];
                a[mt][2] = sA[r*SA + k8 + t + 4];
                a[mt][3] = sA[(r+8)*SA + k8 + t + 4];
            }
            #pragma unroll
            for (int z = 0; z < 3; z++) {
                float* sB = (z==0)?sB0:(z==1)?sB1:sB2;
                #pragma unroll
                for (int nt = 0; nt < 4; nt++) {
                    int cn = n0w + nt*8 + g;
                    float b0 = sB[(k8+t)*SB + cn];
                    float b1 = sB[(k8+t+4)*SB + cn];
                    #pragma unroll
                    for (int mt = 0; mt < 2; mt++)
                        mma8(acc[z][mt][nt], a[mt][0],a[mt][1],a[mt][2],a[mt][3], b0, b1);
                }
            }
        }
    }
    #pragma unroll
    for (int z = 0; z < 3; z++) {
        const float* bias = (z==0)?bq:(z==1)?bk:bv;
        float* out = (z==0)?g_q:(z==1)?g_k:g_v;
        float scl = (z==0)?QSCALE_:1.f;
        #pragma unroll
        for (int mt = 0; mt < 2; mt++) {
            int r = m0 + m0w + mt*16 + g;
            #pragma unroll
            for (int nt = 0; nt < 4; nt++) {
                int c = d0 + n0w + nt*8 + 2*t;
                float b0v = bias[c], b1v = bias[c+1];
                float2 v;
                v.x = f2t((acc[z][mt][nt][0]+b0v)*scl);
                v.y = f2t((acc[z][mt][nt][1]+b1v)*scl);
                *(float2*)&out[(size_t)r*C_ + c] = v;
                v.x = f2t((acc[z][mt][nt][2]+b0v)*scl);
                v.y = f2t((acc[z][mt][nt][3]+b1v)*scl);
                *(float2*)&out[(size_t)(r+8)*C_ + c] = v;
            }
        }
    }
}

// ---------------- Kernel 3: attention, tf32 mma.sync, max-free softmax -----
#define SQ 68
#define SKK 68
#define SV 72
#define SP 72
__global__ __launch_bounds__(256) void attn_kernel()
{
    extern __shared__ float sm[];
    float* sQ = sm;                 // 64 x SQ
    float* sK = sQ + 64*SQ;         // 64 x SKK
    float* sV = sK + 64*SKK;        // 64 x SV
    float* sP = sV + 64*SV;         // 64 x SP
    __shared__ float lred[2][32][4];
    int q0 = blockIdx.x*64;
    int bh = blockIdx.y, b = bh>>2, h = bh&3;
    size_t base = (size_t)b*HW_*C_ + (size_t)h*DH_;
    int tid = threadIdx.x, wid = tid>>5, lane = tid&31;
    int g = lane>>2, t = lane&3;
    int mw = wid>>2, nw = wid&3;
    int q0w = mw*32;

    for (int f = tid; f < 1024; f += 256) {
        int row = f>>4, c4 = (f&15)*4;
        *(float4*)&sQ[row*SQ + c4] =
            *(const float4*)&g_q[base + (size_t)(q0+row)*C_ + c4];
    }

    float o[2][2][4];
    float lp[2][2] = {{0.f,0.f},{0.f,0.f}};
    #pragma unroll
    for (int mt = 0; mt < 2; mt++)
        #pragma unroll
        for (int nt = 0; nt < 2; nt++)
            #pragma unroll
            for (int i = 0; i < 4; i++) o[mt][nt][i] = 0.f;

    for (int kt = 0; kt < 16; kt++) {
        __syncthreads();
        for (int f = tid; f < 1024; f += 256) {
            int row = f>>4, c4 = (f&15)*4;
            *(float4*)&sK[row*SKK + c4] =
                *(const float4*)&g_k[base + (size_t)(kt*64+row)*C_ + c4];
            *(float4*)&sV[row*SV + c4] =
                *(const float4*)&g_v[base + (size_t)(kt*64+row)*C_ + c4];
        }
        __syncthreads();

        float s_[2][2][4] = {};
        #pragma unroll
        for (int s = 0; s < 8; s++) {
            int k8 = s*8;
            float a[2][4];
            #pragma unroll
            for (int mt = 0; mt < 2; mt++) {
                int r = q0w + mt*16 + g;
                a[mt][0] = sQ[r*SQ + k8 + t];
                a[mt][1] = sQ[(r+8)*SQ + k8 + t];
                a[mt][2] = sQ[r*SQ + k8 + t + 4];
                a[mt][3] = sQ[(r+8)*SQ + k8 + t + 4];
            }
            #pragma unroll
            for (int nt = 0; nt < 2; nt++) {
                int key = nw*16 + nt*8 + g;
                float b0 = sK[key*SKK + k8 + t];
                float b1 = sK[key*SKK + k8 + t + 4];
                #pragma unroll
                for (int mt = 0; mt < 2; mt++)
                    mma8(s_[mt][nt], a[mt][0],a[mt][1],a[mt][2],a[mt][3], b0, b1);
            }
        }
        #pragma unroll
        for (int mt = 0; mt < 2; mt++) {
            int r = q0w + mt*16 + g;
            #pragma unroll
            for (int nt = 0; nt < 2; nt++) {
                int c = nw*16 + nt*8 + 2*t;
                float e0 = __expf(s_[mt][nt][0]);
                float e1 = __expf(s_[mt][nt][1]);
                float e2 = __expf(s_[mt][nt][2]);
                float e3 = __expf(s_[mt][nt][3]);
                lp[mt][0] += e0 + e1;
                lp[mt][1] += e2 + e3;
                *(float2*)&sP[r*SP + c]     = make_float2(f2t(e0), f2t(e1));
                *(float2*)&sP[(r+8)*SP + c] = make_float2(f2t(e2), f2t(e3));
            }
        }
        __syncthreads();
        #pragma unroll
        for (int s = 0; s < 8; s++) {
            int k8 = s*8;
            float a[2][4];
            #pragma unroll
            for (int mt = 0; mt < 2; mt++) {
                int r = q0w + mt*16 + g;
                a[mt][0] = sP[r*SP + k8 + t];
                a[mt][1] = sP[(r+8)*SP + k8 + t];
                a[mt][2] = sP[r*SP + k8 + t + 4];
                a[mt][3] = sP[(r+8)*SP + k8 + t + 4];
            }
            #pragma unroll
            for (int nt = 0; nt < 2; nt++) {
                int cn = nw*16 + nt*8 + g;
                float b0 = sV[(k8+t)*SV + cn];
                float b1 = sV[(k8+t+4)*SV + cn];
                #pragma unroll
                for (int mt = 0; mt < 2; mt++)
                    mma8(o[mt][nt], a[mt][0],a[mt][1],a[mt][2],a[mt][3], b0, b1);
            }
        }
    }

    // row-sum reduce: over lanes t (same g), then over 4 n-warps via smem
    #pragma unroll
    for (int mt = 0; mt < 2; mt++)
        #pragma unroll
        for (int rh = 0; rh < 2; rh++) {
            lp[mt][rh] += __shfl_xor_sync(0xffffffffu, lp[mt][rh], 1);
            lp[mt][rh] += __shfl_xor_sync(0xffffffffu, lp[mt][rh], 2);
        }
    if (t == 0) {
        #pragma unroll
        for (int mt = 0; mt < 2; mt++) {
            lred[mw][mt*16+g][nw]   = lp[mt][0];
            lred[mw][mt*16+g+8][nw] = lp[mt][1];
        }
    }
    __syncthreads();
    #pragma unroll
    for (int mt = 0; mt < 2; mt++)
        #pragma unroll
        for (int rh = 0; rh < 2; rh++) {
            int rl = mt*16 + g + rh*8;
            float l = lred[mw][rl][0] + lred[mw][rl][1]
                    + lred[mw][rl][2] + lred[mw][rl][3];
            float inv = 1.f / l;
            int row = q0 + q0w + rl;
            #pragma unroll
            for (int nt = 0; nt < 2; nt++) {
                int c = nw*16 + nt*8 + 2*t;
                float2 v;
                v.x = f2t(o[mt][nt][rh*2+0] * inv);
                v.y = f2t(o[mt][nt][rh*2+1] * inv);
                *(float2*)&g_h[base + (size_t)row*C_ + c] = v;
            }
        }
}

// ---------------- Kernel 4: proj + bias + residual ----------------
__global__ __launch_bounds__(256) void proj_kernel(
    const float* __restrict__ Wp, const float* __restrict__ bp,
    const float* __restrict__ x, float* __restrict__ out)
{
    extern __shared__ float sm[];
    float* sA = sm;                 // 128 x SA
    float* sB = sm + 128*SA;        // 32 x SB
    int d0 = blockIdx.x*64, m0 = blockIdx.y*128;
    int tid = threadIdx.x, wid = tid>>5, lane = tid&31;
    int g = lane>>2, t = lane&3;
    int m0w = (wid>>1)*32, n0w = (wid&1)*32;

    float acc[2][4][4];
    #pragma unroll
    for (int mt = 0; mt < 2; mt++)
        #pragma unroll
        for (int nt = 0; nt < 4; nt++)
            #pragma unroll
            for (int i = 0; i < 4; i++) acc[mt][nt][i] = 0.f;

    for (int kc = 0; kc < 8; kc++) {
        int k0 = kc*32;
        __syncthreads();
        for (int f = tid; f < 1024; f += 256) {
            int row = f>>3, c4 = (f&7)*4;
            *(float4*)&sA[row*SA + c4] =
                *(const float4*)&g_h[(size_t)(m0+row)*C_ + k0 + c4];
        }
        for (int f = tid; f < 512; f += 256) {
            int row = f>>4, c4 = (f&15)*4;
            float4 w = *(const float4*)&Wp[(size_t)(k0+row)*C_ + d0 + c4];
            w.x=f2t(w.x); w.y=f2t(w.y); w.z=f2t(w.z); w.w=f2t(w.w);
            *(float4*)&sB[row*SB + c4] = w;
        }
        __syncthreads();
        #pragma unroll
        for (int s = 0; s < 4; s++) {
            int k8 = s*8;
            float a[2][4];
            #pragma unroll
            for (int mt = 0; mt < 2; mt++) {
                int r = m0w + mt*16 + g;
                a[mt][0] = sA[r*SA + k8 + t];
                a[mt][1] = sA[(r+8)*SA + k8 + t];
                a[mt][2] = sA[r*SA + k8 + t + 4];
                a[mt][3] = sA[(r+8)*SA + k8 + t + 4];
            }
            #pragma unroll
            for (int nt = 0; nt < 4; nt++) {
                int cn = n0w + nt*8 + g;
                float b0 = sB[(k8+t)*SB + cn];
                float b1 = sB[(k8+t+4)*SB + cn];
                #pragma unroll
                for (int mt = 0; mt < 2; mt++)
                    mma8(acc[mt][nt], a[mt][0],a[mt][1],a[mt][2],a[mt][3], b0, b1);
            }
        }
    }
    #pragma unroll
    for (int mt = 0; mt < 2; mt++) {
        #pragma unroll
        for (int rh = 0; rh < 2; rh++) {
            int r = m0 + m0w + mt*16 + g + rh*8;
            int bt = r >> 10, n = r & 1023;
            #pragma unroll
            for (int nt = 0; nt < 4; nt++) {
                int d = d0 + n0w + nt*8 + 2*t;
                size_t i0 = ((size_t)bt*C_ + d)*HW_ + n;
                size_t i1 = i0 + HW_;
                out[i0] = (acc[mt][nt][rh*2+0] + bp[d]   + x[i0]) * RS2_;
                out[i1] = (acc[mt][nt][rh*2+1] + bp[d+1] + x[i1]) * RS2_;
            }
        }
    }
}

// ---------------------------------------------------------------------------
extern "C" void kernel_launch(void* const* d_in, const int* in_sizes, int n_in,
                              void* d_out, int out_size)
{
    const float* x   = (const float*)d_in[0];
    const float* gns = (const float*)d_in[1];
    const float* gnb = (const float*)d_in[2];
    const float* Wq  = (const float*)d_in[3];
    const float* bq  = (const float*)d_in[4];
    const float* Wk  = (const float*)d_in[5];
    const float* bk  = (const float*)d_in[6];
    const float* Wv  = (const float*)d_in[7];
    const float* bv  = (const float*)d_in[8];
    const float* Wp  = (const float*)d_in[9];
    const float* bp  = (const float*)d_in[10];
    float* out = (float*)d_out;

    const int smem_qkv  = (128*SA + 3*32*SB) * 4;
    const int smem_attn = (64*SQ + 64*SKK + 64*SV + 64*SP) * 4;
    const int smem_proj = (128*SA + 32*SB) * 4;

    cudaFuncSetAttribute(attn_kernel, cudaFuncAttributeMaxDynamicSharedMemorySize, smem_attn);

    gn_kernel  <<<B_*GROUPS_, 256>>>(x, gns, gnb);
    qkv_kernel <<<dim3(4, 128), 256, smem_qkv>>>(Wq, bq, Wk, bk, Wv, bv);
    attn_kernel<<<dim3(16, 64), 256, smem_attn>>>();
    proj_kernel<<<dim3(4, 128), 256, smem_proj>>>(Wp, bp, x, out);
}

// round 5
// speedup vs baseline: 4.4670x; 1.9502x over previous
#include <cuda_runtime.h>
#include <cuda_bf16.h>
#include <cstdint>
#include <math.h>

#define B_   16
#define C_   256
#define HW_  1024
#define HEADS_ 4
#define DH_  64
#define GROUPS_ 32
#define CPG_ 8
#define EPS_ 1e-6f
#define RS2_ 0.70710678118654752440f
#define QSCALE_ (1.0f/16.0f)

typedef __nv_bfloat16 bf16;

// ---------------- scratch ----------------
__device__ bf16 g_xn[B_*HW_*C_];
__device__ bf16 g_q [B_*HW_*C_];   // pre-scaled by 1/16
__device__ bf16 g_k [B_*HW_*C_];
__device__ bf16 g_v [B_*HW_*C_];
__device__ bf16 g_h [B_*HW_*C_];
__device__ bf16 g_wt[4*C_*C_];     // W^T: [z][cout][cin]
__device__ bf16 g_vt[B_*HEADS_*DH_*HW_]; // V^T per (b,h): [d][token]

// ---------------- helpers ----------------
__device__ __forceinline__ uint32_t pk2(float lo, float hi){
    uint32_t d;
    asm("cvt.rn.bf16x2.f32 %0, %1, %2;" : "=r"(d) : "f"(hi), "f"(lo));
    return d;
}
// D += A(16x16,row) * B(16x8,col)  bf16, fp32 accum
__device__ __forceinline__ void mma16(float* c, uint32_t a0, uint32_t a1,
                                      uint32_t a2, uint32_t a3,
                                      uint32_t b0, uint32_t b1){
    asm volatile("mma.sync.aligned.m16n8k16.row.col.f32.bf16.bf16.f32 "
        "{%0,%1,%2,%3}, {%4,%5,%6,%7}, {%8,%9}, {%0,%1,%2,%3};"
        : "+f"(c[0]), "+f"(c[1]), "+f"(c[2]), "+f"(c[3])
        : "r"(a0), "r"(a1), "r"(a2), "r"(a3), "r"(b0), "r"(b1));
}
__device__ __forceinline__ uint32_t lduint(const bf16* p){
    return *(const uint32_t*)p;
}

// ---------------- Kernel 1: GroupNorm -> (B,N,C) bf16 ----------------
__global__ __launch_bounds__(256) void gn_kernel(
    const float* __restrict__ x, const float* __restrict__ sc,
    const float* __restrict__ bi)
{
    __shared__ float xs[CPG_*HW_];
    __shared__ float red[64];
    int b = blockIdx.x >> 5, g = blockIdx.x & 31;
    const float* base = x + (size_t)b*C_*HW_ + (size_t)g*CPG_*HW_;
    int tid = threadIdx.x;
    float s = 0.f, sq = 0.f;
    #pragma unroll 8
    for (int i = tid; i < CPG_*HW_; i += 256) {
        float v = base[i]; xs[i] = v; s += v; sq += v*v;
    }
    #pragma unroll
    for (int o = 16; o; o >>= 1) {
        s  += __shfl_xor_sync(0xffffffffu, s,  o);
        sq += __shfl_xor_sync(0xffffffffu, sq, o);
    }
    int w = tid >> 5;
    if ((tid & 31) == 0) { red[w] = s; red[32+w] = sq; }
    __syncthreads();
    if (tid < 32) {
        s  = (tid < 8) ? red[tid]    : 0.f;
        sq = (tid < 8) ? red[32+tid] : 0.f;
        #pragma unroll
        for (int o = 4; o; o >>= 1) {
            s  += __shfl_xor_sync(0xffffffffu, s,  o);
            sq += __shfl_xor_sync(0xffffffffu, sq, o);
        }
        if (tid == 0) { red[0] = s; red[1] = sq; }
    }
    __syncthreads();
    float mean = red[0] * (1.f/8192.f);
    float var  = red[1] * (1.f/8192.f) - mean*mean;
    float rinv = rsqrtf(var + EPS_);
    float scs[CPG_], bis[CPG_];
    #pragma unroll
    for (int c = 0; c < CPG_; c++) { scs[c] = sc[g*CPG_+c]; bis[c] = bi[g*CPG_+c]; }
    for (int n = tid; n < HW_; n += 256) {
        float buf[CPG_];
        #pragma unroll
        for (int c = 0; c < CPG_; c++)
            buf[c] = (xs[c*HW_+n] - mean)*rinv*scs[c] + bis[c];
        uint4 u;
        u.x = pk2(buf[0],buf[1]); u.y = pk2(buf[2],buf[3]);
        u.z = pk2(buf[4],buf[5]); u.w = pk2(buf[6],buf[7]);
        *(uint4*)&g_xn[((size_t)(b*HW_+n))*C_ + g*CPG_] = u;
    }
}

// ---------------- Kernel 2: weight transpose -> bf16 [cout][cin] ----------
__global__ void wt_kernel(const float* __restrict__ Wq, const float* __restrict__ Wk,
                          const float* __restrict__ Wv, const float* __restrict__ Wp)
{
    __shared__ float t[32][33];
    int z = blockIdx.z;
    const float* W = (z==0)?Wq:(z==1)?Wk:(z==2)?Wv:Wp;
    bf16* WT = g_wt + (size_t)z*C_*C_;
    int x0 = blockIdx.x*32, y0 = blockIdx.y*32;
    int tx = threadIdx.x, ty = threadIdx.y;
    #pragma unroll
    for (int i = 0; i < 4; i++)
        t[ty+8*i][tx] = W[(size_t)(y0+ty+8*i)*C_ + x0+tx];
    __syncthreads();
    #pragma unroll
    for (int i = 0; i < 4; i++)
        WT[(size_t)(x0+ty+8*i)*C_ + y0+tx] = __float2bfloat16_rn(t[tx][ty+8*i]);
}

// ---------------- Kernel 3: fused QKV, bf16 mma ----------------
#define SAE 40
#define SBE 40
__global__ __launch_bounds__(256) void qkv_kernel(
    const float* __restrict__ bq, const float* __restrict__ bk,
    const float* __restrict__ bv)
{
    extern __shared__ bf16 smb[];
    bf16* sA  = smb;                    // [128][SAE]
    bf16* sB0 = sA  + 128*SAE;          // [64][SBE] x3
    bf16* sB1 = sB0 + 64*SBE;
    bf16* sB2 = sB1 + 64*SBE;
    int d0 = blockIdx.x*64, m0 = blockIdx.y*128;
    int tid = threadIdx.x, wid = tid>>5, lane = tid&31;
    int g = lane>>2, t = lane&3;
    int m0w = (wid>>1)*32, n0w = (wid&1)*32;

    float acc[3][2][4][4];
    #pragma unroll
    for (int z = 0; z < 3; z++)
        #pragma unroll
        for (int mt = 0; mt < 2; mt++)
            #pragma unroll
            for (int nt = 0; nt < 4; nt++)
                #pragma unroll
                for (int i = 0; i < 4; i++) acc[z][mt][nt][i] = 0.f;

    for (int kc = 0; kc < 8; kc++) {
        int k0 = kc*32;
        __syncthreads();
        #pragma unroll
        for (int i = 0; i < 2; i++) {                 // A: 128x32 bf16
            int f = tid + i*256;
            int row = f>>2, seg = (f&3)*8;
            *(uint4*)&sA[row*SAE + seg] =
                *(const uint4*)&g_xn[(size_t)(m0+row)*C_ + k0 + seg];
        }
        {                                             // B: 64n x 32k each
            int n = tid>>2, seg = (tid&3)*8;
            size_t off = (size_t)(d0+n)*C_ + k0 + seg;
            *(uint4*)&sB0[n*SBE + seg] = *(const uint4*)&g_wt[off];
            *(uint4*)&sB1[n*SBE + seg] = *(const uint4*)&g_wt[C_*C_ + off];
            *(uint4*)&sB2[n*SBE + seg] = *(const uint4*)&g_wt[2*C_*C_ + off];
        }
        __syncthreads();
        #pragma unroll
        for (int s = 0; s < 2; s++) {
            int kk = s*16;
            uint32_t a[2][4];
            #pragma unroll
            for (int mt = 0; mt < 2; mt++) {
                int r = m0w + mt*16 + g;
                a[mt][0] = lduint(&sA[r*SAE + kk + 2*t]);
                a[mt][1] = lduint(&sA[(r+8)*SAE + kk + 2*t]);
                a[mt][2] = lduint(&sA[r*SAE + kk + 2*t + 8]);
                a[mt][3] = lduint(&sA[(r+8)*SAE + kk + 2*t + 8]);
            }
            #pragma unroll
            for (int z = 0; z < 3; z++) {
                bf16* sB = (z==0)?sB0:(z==1)?sB1:sB2;
                #pragma unroll
                for (int nt = 0; nt < 4; nt++) {
                    int cn = n0w + nt*8 + g;
                    uint32_t b0 = lduint(&sB[cn*SBE + kk + 2*t]);
                    uint32_t b1 = lduint(&sB[cn*SBE + kk + 2*t + 8]);
                    #pragma unroll
                    for (int mt = 0; mt < 2; mt++)
                        mma16(acc[z][mt][nt], a[mt][0],a[mt][1],a[mt][2],a[mt][3], b0, b1);
                }
            }
        }
    }
    #pragma unroll
    for (int z = 0; z < 3; z++) {
        const float* bias = (z==0)?bq:(z==1)?bk:bv;
        bf16* out = (z==0)?g_q:(z==1)?g_k:g_v;
        float scl = (z==0)?QSCALE_:1.f;
        #pragma unroll
        for (int mt = 0; mt < 2; mt++) {
            int r = m0 + m0w + mt*16 + g;
            #pragma unroll
            for (int nt = 0; nt < 4; nt++) {
                int c = d0 + n0w + nt*8 + 2*t;
                float b0v = bias[c], b1v = bias[c+1];
                *(uint32_t*)&out[(size_t)r*C_ + c] =
                    pk2((acc[z][mt][nt][0]+b0v)*scl, (acc[z][mt][nt][1]+b1v)*scl);
                *(uint32_t*)&out[(size_t)(r+8)*C_ + c] =
                    pk2((acc[z][mt][nt][2]+b0v)*scl, (acc[z][mt][nt][3]+b1v)*scl);
            }
        }
    }
}

// ---------------- Kernel 4: V transpose -> g_vt[bh][d][tok] bf16 ----------
__global__ void vt_kernel()
{
    __shared__ bf16 t[32][33];
    int ttile = blockIdx.x, dtile = blockIdx.y, bh = blockIdx.z;
    int b = bh >> 2, h = bh & 3;
    int tx = threadIdx.x, ty = threadIdx.y;
    #pragma unroll
    for (int i = 0; i < 4; i++)
        t[ty+8*i][tx] = g_v[(size_t)(b*HW_ + ttile*32 + ty+8*i)*C_ + h*DH_ + dtile*32 + tx];
    __syncthreads();
    #pragma unroll
    for (int i = 0; i < 4; i++)
        g_vt[(size_t)bh*DH_*HW_ + (size_t)(dtile*32 + ty+8*i)*HW_ + ttile*32 + tx]
            = t[tx][ty+8*i];
}

// ---------------- Kernel 5: attention, bf16 mma, max-free softmax ----------
#define SQE 72
__global__ __launch_bounds__(256) void attn_kernel()
{
    extern __shared__ bf16 smb[];
    bf16* sQ  = smb;               // [64][SQE]
    bf16* sK  = sQ  + 64*SQE;
    bf16* sVt = sK  + 64*SQE;      // [d=64][j=64]
    bf16* sP  = sVt + 64*SQE;
    __shared__ float lred[2][32][4];
    int q0 = blockIdx.x*64;
    int bh = blockIdx.y, b = bh>>2, h = bh&3;
    size_t base = (size_t)b*HW_*C_ + (size_t)h*DH_;
    const bf16* vtb = g_vt + (size_t)bh*DH_*HW_;
    int tid = threadIdx.x, wid = tid>>5, lane = tid&31;
    int g = lane>>2, t = lane&3;
    int mw = wid>>2, nw = wid&3;
    int q0w = mw*32;
    int lrow = tid>>3, lseg = (tid&7)*8;   // tile-fill mapping (2 per thread)

    #pragma unroll
    for (int i = 0; i < 2; i++) {
        int f = tid + i*256, row = f>>3, seg = (f&7)*8;
        *(uint4*)&sQ[row*SQE + seg] =
            *(const uint4*)&g_q[base + (size_t)(q0+row)*C_ + seg];
    }

    float o[2][2][4];
    float lp[2][2] = {{0.f,0.f},{0.f,0.f}};
    #pragma unroll
    for (int mt = 0; mt < 2; mt++)
        #pragma unroll
        for (int nt = 0; nt < 2; nt++)
            #pragma unroll
            for (int i = 0; i < 4; i++) o[mt][nt][i] = 0.f;

    // prefetch kt=0
    uint4 kreg[2], vreg[2];
    #pragma unroll
    for (int i = 0; i < 2; i++) {
        int f = tid + i*256, row = f>>3, seg = (f&7)*8;
        kreg[i] = *(const uint4*)&g_k[base + (size_t)(row)*C_ + seg];
        vreg[i] = *(const uint4*)&vtb[(size_t)row*HW_ + seg];
    }

    for (int kt = 0; kt < 16; kt++) {
        __syncthreads();
        #pragma unroll
        for (int i = 0; i < 2; i++) {
            int f = tid + i*256, row = f>>3, seg = (f&7)*8;
            *(uint4*)&sK[row*SQE + seg]  = kreg[i];
            *(uint4*)&sVt[row*SQE + seg] = vreg[i];
        }
        __syncthreads();
        if (kt < 15) {
            #pragma unroll
            for (int i = 0; i < 2; i++) {
                int f = tid + i*256, row = f>>3, seg = (f&7)*8;
                kreg[i] = *(const uint4*)&g_k[base + (size_t)((kt+1)*64+row)*C_ + seg];
                vreg[i] = *(const uint4*)&vtb[(size_t)row*HW_ + (kt+1)*64 + seg];
            }
        }

        float s_[2][2][4] = {};
        #pragma unroll
        for (int s = 0; s < 4; s++) {
            int kk = s*16;
            uint32_t a[2][4];
            #pragma unroll
            for (int mt = 0; mt < 2; mt++) {
                int r = q0w + mt*16 + g;
                a[mt][0] = lduint(&sQ[r*SQE + kk + 2*t]);
                a[mt][1] = lduint(&sQ[(r+8)*SQE + kk + 2*t]);
                a[mt][2] = lduint(&sQ[r*SQE + kk + 2*t + 8]);
                a[mt][3] = lduint(&sQ[(r+8)*SQE + kk + 2*t + 8]);
            }
            #pragma unroll
            for (int nt = 0; nt < 2; nt++) {
                int key = nw*16 + nt*8 + g;
                uint32_t b0 = lduint(&sK[key*SQE + kk + 2*t]);
                uint32_t b1 = lduint(&sK[key*SQE + kk + 2*t + 8]);
                #pragma unroll
                for (int mt = 0; mt < 2; mt++)
                    mma16(s_[mt][nt], a[mt][0],a[mt][1],a[mt][2],a[mt][3], b0, b1);
            }
        }
        #pragma unroll
        for (int mt = 0; mt < 2; mt++) {
            int r = q0w + mt*16 + g;
            #pragma unroll
            for (int nt = 0; nt < 2; nt++) {
                int c = nw*16 + nt*8 + 2*t;
                float e0 = __expf(s_[mt][nt][0]);
                float e1 = __expf(s_[mt][nt][1]);
                float e2 = __expf(s_[mt][nt][2]);
                float e3 = __expf(s_[mt][nt][3]);
                lp[mt][0] += e0 + e1;
                lp[mt][1] += e2 + e3;
                *(uint32_t*)&sP[r*SQE + c]     = pk2(e0, e1);
                *(uint32_t*)&sP[(r+8)*SQE + c] = pk2(e2, e3);
            }
        }
        __syncthreads();
        #pragma unroll
        for (int s = 0; s < 4; s++) {
            int kk = s*16;
            uint32_t a[2][4];
            #pragma unroll
            for (int mt = 0; mt < 2; mt++) {
                int r = q0w + mt*16 + g;
                a[mt][0] = lduint(&sP[r*SQE + kk + 2*t]);
                a[mt][1] = lduint(&sP[(r+8)*SQE + kk + 2*t]);
                a[mt][2] = lduint(&sP[r*SQE + kk + 2*t + 8]);
                a[mt][3] = lduint(&sP[(r+8)*SQE + kk + 2*t + 8]);
            }
            #pragma unroll
            for (int nt = 0; nt < 2; nt++) {
                int cn = nw*16 + nt*8 + g;
                uint32_t b0 = lduint(&sVt[cn*SQE + kk + 2*t]);
                uint32_t b1 = lduint(&sVt[cn*SQE + kk + 2*t + 8]);
                #pragma unroll
                for (int mt = 0; mt < 2; mt++)
                    mma16(o[mt][nt], a[mt][0],a[mt][1],a[mt][2],a[mt][3], b0, b1);
            }
        }
    }

    #pragma unroll
    for (int mt = 0; mt < 2; mt++)
        #pragma unroll
        for (int rh = 0; rh < 2; rh++) {
            lp[mt][rh] += __shfl_xor_sync(0xffffffffu, lp[mt][rh], 1);
            lp[mt][rh] += __shfl_xor_sync(0xffffffffu, lp[mt][rh], 2);
        }
    if (t == 0) {
        #pragma unroll
        for (int mt = 0; mt < 2; mt++) {
            lred[mw][mt*16+g][nw]   = lp[mt][0];
            lred[mw][mt*16+g+8][nw] = lp[mt][1];
        }
    }
    __syncthreads();
    #pragma unroll
    for (int mt = 0; mt < 2; mt++)
        #pragma unroll
        for (int rh = 0; rh < 2; rh++) {
            int rl = mt*16 + g + rh*8;
            float l = lred[mw][rl][0] + lred[mw][rl][1]
                    + lred[mw][rl][2] + lred[mw][rl][3];
            float inv = 1.f / l;
            int row = q0 + q0w + rl;
            #pragma unroll
            for (int nt = 0; nt < 2; nt++) {
                int c = nw*16 + nt*8 + 2*t;
                *(uint32_t*)&g_h[base + (size_t)row*C_ + c] =
                    pk2(o[mt][nt][rh*2+0]*inv, o[mt][nt][rh*2+1]*inv);
            }
        }
}

// ---------------- Kernel 6: proj + bias + residual ----------------
__global__ __launch_bounds__(256) void proj_kernel(
    const float* __restrict__ bp, const float* __restrict__ x,
    float* __restrict__ out)
{
    extern __shared__ bf16 smb[];
    bf16* sA = smb;                 // [128][SAE]
    bf16* sB = sA + 128*SAE;        // [64][SBE]
    const bf16* WT = g_wt + (size_t)3*C_*C_;
    int d0 = blockIdx.x*64, m0 = blockIdx.y*128;
    int tid = threadIdx.x, wid = tid>>5, lane = tid&31;
    int g = lane>>2, t = lane&3;
    int m0w = (wid>>1)*32, n0w = (wid&1)*32;

    float acc[2][4][4];
    #pragma unroll
    for (int mt = 0; mt < 2; mt++)
        #pragma unroll
        for (int nt = 0; nt < 4; nt++)
            #pragma unroll
            for (int i = 0; i < 4; i++) acc[mt][nt][i] = 0.f;

    for (int kc = 0; kc < 8; kc++) {
        int k0 = kc*32;
        __syncthreads();
        #pragma unroll
        for (int i = 0; i < 2; i++) {
            int f = tid + i*256, row = f>>2, seg = (f&3)*8;
            *(uint4*)&sA[row*SAE + seg] =
                *(const uint4*)&g_h[(size_t)(m0+row)*C_ + k0 + seg];
        }
        {
            int n = tid>>2, seg = (tid&3)*8;
            *(uint4*)&sB[n*SBE + seg] =
                *(const uint4*)&WT[(size_t)(d0+n)*C_ + k0 + seg];
        }
        __syncthreads();
        #pragma unroll
        for (int s = 0; s < 2; s++) {
            int kk = s*16;
            uint32_t a[2][4];
            #pragma unroll
            for (int mt = 0; mt < 2; mt++) {
                int r = m0w + mt*16 + g;
                a[mt][0] = lduint(&sA[r*SAE + kk + 2*t]);
                a[mt][1] = lduint(&sA[(r+8)*SAE + kk + 2*t]);
                a[mt][2] = lduint(&sA[r*SAE + kk + 2*t + 8]);
                a[mt][3] = lduint(&sA[(r+8)*SAE + kk + 2*t + 8]);
            }
            #pragma unroll
            for (int nt = 0; nt < 4; nt++) {
                int cn = n0w + nt*8 + g;
                uint32_t b0 = lduint(&sB[cn*SBE + kk + 2*t]);
                uint32_t b1 = lduint(&sB[cn*SBE + kk + 2*t + 8]);
                #pragma unroll
                for (int mt = 0; mt < 2; mt++)
                    mma16(acc[mt][nt], a[mt][0],a[mt][1],a[mt][2],a[mt][3], b0, b1);
            }
        }
    }
    #pragma unroll
    for (int mt = 0; mt < 2; mt++) {
        #pragma unroll
        for (int rh = 0; rh < 2; rh++) {
            int r = m0 + m0w + mt*16 + g + rh*8;
            int bt = r >> 10, n = r & 1023;
            #pragma unroll
            for (int nt = 0; nt < 4; nt++) {
                int d = d0 + n0w + nt*8 + 2*t;
                size_t i0 = ((size_t)bt*C_ + d)*HW_ + n;
                size_t i1 = i0 + HW_;
                out[i0] = (acc[mt][nt][rh*2+0] + bp[d]   + x[i0]) * RS2_;
                out[i1] = (acc[mt][nt][rh*2+1] + bp[d+1] + x[i1]) * RS2_;
            }
        }
    }
}

// ---------------------------------------------------------------------------
extern "C" void kernel_launch(void* const* d_in, const int* in_sizes, int n_in,
                              void* d_out, int out_size)
{
    const float* x   = (const float*)d_in[0];
    const float* gns = (const float*)d_in[1];
    const float* gnb = (const float*)d_in[2];
    const float* Wq  = (const float*)d_in[3];
    const float* bq  = (const float*)d_in[4];
    const float* Wk  = (const float*)d_in[5];
    const float* bk  = (const float*)d_in[6];
    const float* Wv  = (const float*)d_in[7];
    const float* bv  = (const float*)d_in[8];
    const float* Wp  = (const float*)d_in[9];
    const float* bp  = (const float*)d_in[10];
    float* out = (float*)d_out;

    const int smem_qkv  = (128*SAE + 3*64*SBE) * 2;
    const int smem_attn = (4*64*SQE) * 2;
    const int smem_proj = (128*SAE + 64*SBE) * 2;

    gn_kernel  <<<B_*GROUPS_, 256>>>(x, gns, gnb);
    wt_kernel  <<<dim3(8,8,4), dim3(32,8)>>>(Wq, Wk, Wv, Wp);
    qkv_kernel <<<dim3(4, 128), 256, smem_qkv>>>(bq, bk, bv);
    vt_kernel  <<<dim3(32,2,64), dim3(32,8)>>>();
    attn_kernel<<<dim3(16, 64), 256, smem_attn>>>();
    proj_kernel<<<dim3(4, 128), 256, smem_proj>>>(bp, x, out);
}

// round 6
// speedup vs baseline: 5.0483x; 1.1301x over previous
#include <cuda_runtime.h>
#include <cuda_bf16.h>
#include <cstdint>
#include <math.h>

#define B_   16
#define C_   256
#define HW_  1024
#define HEADS_ 4
#define DH_  64
#define GROUPS_ 32
#define CPG_ 8
#define EPS_ 1e-6f
#define RS2_ 0.70710678118654752440f
#define QSCALE_ (1.0f/16.0f)

typedef __nv_bfloat16 bf16;

// ---------------- scratch ----------------
__device__ bf16 g_xn[B_*HW_*C_];
__device__ bf16 g_q [B_*HW_*C_];   // pre-scaled by 1/16
__device__ bf16 g_k [B_*HW_*C_];
__device__ bf16 g_v [B_*HW_*C_];
__device__ bf16 g_h [B_*HW_*C_];
__device__ bf16 g_wt[4*C_*C_];     // W^T: [z][cout][cin]
__device__ bf16 g_vt[B_*HEADS_*DH_*HW_]; // V^T per (b,h): [d][token]

// ---------------- helpers ----------------
__device__ __forceinline__ uint32_t pk2(float lo, float hi){
    uint32_t d;
    asm("cvt.rn.bf16x2.f32 %0, %1, %2;" : "=r"(d) : "f"(hi), "f"(lo));
    return d;
}
__device__ __forceinline__ void mma16(float* c, uint32_t a0, uint32_t a1,
                                      uint32_t a2, uint32_t a3,
                                      uint32_t b0, uint32_t b1){
    asm volatile("mma.sync.aligned.m16n8k16.row.col.f32.bf16.bf16.f32 "
        "{%0,%1,%2,%3}, {%4,%5,%6,%7}, {%8,%9}, {%0,%1,%2,%3};"
        : "+f"(c[0]), "+f"(c[1]), "+f"(c[2]), "+f"(c[3])
        : "r"(a0), "r"(a1), "r"(a2), "r"(a3), "r"(b0), "r"(b1));
}
__device__ __forceinline__ uint32_t lduint(const bf16* p){
    return *(const uint32_t*)p;
}

// ---------------- Kernel 1: GroupNorm -> (B,N,C) bf16 ----------------
__global__ __launch_bounds__(256) void gn_kernel(
    const float* __restrict__ x, const float* __restrict__ sc,
    const float* __restrict__ bi)
{
    __shared__ float xs[CPG_*HW_];
    __shared__ float red[64];
    int b = blockIdx.x >> 5, g = blockIdx.x & 31;
    const float* base = x + (size_t)b*C_*HW_ + (size_t)g*CPG_*HW_;
    int tid = threadIdx.x;
    float s = 0.f, sq = 0.f;
    #pragma unroll 8
    for (int i = tid; i < CPG_*HW_; i += 256) {
        float v = base[i]; xs[i] = v; s += v; sq += v*v;
    }
    #pragma unroll
    for (int o = 16; o; o >>= 1) {
        s  += __shfl_xor_sync(0xffffffffu, s,  o);
        sq += __shfl_xor_sync(0xffffffffu, sq, o);
    }
    int w = tid >> 5;
    if ((tid & 31) == 0) { red[w] = s; red[32+w] = sq; }
    __syncthreads();
    if (tid < 32) {
        s  = (tid < 8) ? red[tid]    : 0.f;
        sq = (tid < 8) ? red[32+tid] : 0.f;
        #pragma unroll
        for (int o = 4; o; o >>= 1) {
            s  += __shfl_xor_sync(0xffffffffu, s,  o);
            sq += __shfl_xor_sync(0xffffffffu, sq, o);
        }
        if (tid == 0) { red[0] = s; red[1] = sq; }
    }
    __syncthreads();
    float mean = red[0] * (1.f/8192.f);
    float var  = red[1] * (1.f/8192.f) - mean*mean;
    float rinv = rsqrtf(var + EPS_);
    float scs[CPG_], bis[CPG_];
    #pragma unroll
    for (int c = 0; c < CPG_; c++) { scs[c] = sc[g*CPG_+c]; bis[c] = bi[g*CPG_+c]; }
    for (int n = tid; n < HW_; n += 256) {
        float buf[CPG_];
        #pragma unroll
        for (int c = 0; c < CPG_; c++)
            buf[c] = (xs[c*HW_+n] - mean)*rinv*scs[c] + bis[c];
        uint4 u;
        u.x = pk2(buf[0],buf[1]); u.y = pk2(buf[2],buf[3]);
        u.z = pk2(buf[4],buf[5]); u.w = pk2(buf[6],buf[7]);
        *(uint4*)&g_xn[((size_t)(b*HW_+n))*C_ + g*CPG_] = u;
    }
}

// ---------------- Kernel 2: weight transpose -> bf16 [cout][cin] ----------
__global__ void wt_kernel(const float* __restrict__ Wq, const float* __restrict__ Wk,
                          const float* __restrict__ Wv, const float* __restrict__ Wp)
{
    __shared__ float t[32][33];
    int z = blockIdx.z;
    const float* W = (z==0)?Wq:(z==1)?Wk:(z==2)?Wv:Wp;
    bf16* WT = g_wt + (size_t)z*C_*C_;
    int x0 = blockIdx.x*32, y0 = blockIdx.y*32;
    int tx = threadIdx.x, ty = threadIdx.y;
    #pragma unroll
    for (int i = 0; i < 4; i++)
        t[ty+8*i][tx] = W[(size_t)(y0+ty+8*i)*C_ + x0+tx];
    __syncthreads();
    #pragma unroll
    for (int i = 0; i < 4; i++)
        WT[(size_t)(x0+ty+8*i)*C_ + y0+tx] = __float2bfloat16_rn(t[tx][ty+8*i]);
}

// ---------------- Kernel 3: fused QKV, bf16 mma ----------------
#define SAE 40
#define SBE 40
__global__ __launch_bounds__(256) void qkv_kernel(
    const float* __restrict__ bq, const float* __restrict__ bk,
    const float* __restrict__ bv)
{
    extern __shared__ bf16 smb[];
    bf16* sA  = smb;                    // [128][SAE]
    bf16* sB0 = sA  + 128*SAE;          // [64][SBE] x3
    bf16* sB1 = sB0 + 64*SBE;
    bf16* sB2 = sB1 + 64*SBE;
    int d0 = blockIdx.x*64, m0 = blockIdx.y*128;
    int tid = threadIdx.x, wid = tid>>5, lane = tid&31;
    int g = lane>>2, t = lane&3;
    int m0w = (wid>>1)*32, n0w = (wid&1)*32;

    float acc[3][2][4][4];
    #pragma unroll
    for (int z = 0; z < 3; z++)
        #pragma unroll
        for (int mt = 0; mt < 2; mt++)
            #pragma unroll
            for (int nt = 0; nt < 4; nt++)
                #pragma unroll
                for (int i = 0; i < 4; i++) acc[z][mt][nt][i] = 0.f;

    for (int kc = 0; kc < 8; kc++) {
        int k0 = kc*32;
        __syncthreads();
        #pragma unroll
        for (int i = 0; i < 2; i++) {                 // A: 128x32 bf16
            int f = tid + i*256;
            int row = f>>2, seg = (f&3)*8;
            *(uint4*)&sA[row*SAE + seg] =
                *(const uint4*)&g_xn[(size_t)(m0+row)*C_ + k0 + seg];
        }
        {                                             // B: 64n x 32k each
            int n = tid>>2, seg = (tid&3)*8;
            size_t off = (size_t)(d0+n)*C_ + k0 + seg;
            *(uint4*)&sB0[n*SBE + seg] = *(const uint4*)&g_wt[off];
            *(uint4*)&sB1[n*SBE + seg] = *(const uint4*)&g_wt[C_*C_ + off];
            *(uint4*)&sB2[n*SBE + seg] = *(const uint4*)&g_wt[2*C_*C_ + off];
        }
        __syncthreads();
        #pragma unroll
        for (int s = 0; s < 2; s++) {
            int kk = s*16;
            uint32_t a[2][4];
            #pragma unroll
            for (int mt = 0; mt < 2; mt++) {
                int r = m0w + mt*16 + g;
                a[mt][0] = lduint(&sA[r*SAE + kk + 2*t]);
                a[mt][1] = lduint(&sA[(r+8)*SAE + kk + 2*t]);
                a[mt][2] = lduint(&sA[r*SAE + kk + 2*t + 8]);
                a[mt][3] = lduint(&sA[(r+8)*SAE + kk + 2*t + 8]);
            }
            #pragma unroll
            for (int z = 0; z < 3; z++) {
                bf16* sB = (z==0)?sB0:(z==1)?sB1:sB2;
                #pragma unroll
                for (int nt = 0; nt < 4; nt++) {
                    int cn = n0w + nt*8 + g;
                    uint32_t b0 = lduint(&sB[cn*SBE + kk + 2*t]);
                    uint32_t b1 = lduint(&sB[cn*SBE + kk + 2*t + 8]);
                    #pragma unroll
                    for (int mt = 0; mt < 2; mt++)
                        mma16(acc[z][mt][nt], a[mt][0],a[mt][1],a[mt][2],a[mt][3], b0, b1);
                }
            }
        }
    }
    #pragma unroll
    for (int z = 0; z < 3; z++) {
        const float* bias = (z==0)?bq:(z==1)?bk:bv;
        bf16* out = (z==0)?g_q:(z==1)?g_k:g_v;
        float scl = (z==0)?QSCALE_:1.f;
        #pragma unroll
        for (int mt = 0; mt < 2; mt++) {
            int r = m0 + m0w + mt*16 + g;
            #pragma unroll
            for (int nt = 0; nt < 4; nt++) {
                int c = d0 + n0w + nt*8 + 2*t;
                float b0v = bias[c], b1v = bias[c+1];
                *(uint32_t*)&out[(size_t)r*C_ + c] =
                    pk2((acc[z][mt][nt][0]+b0v)*scl, (acc[z][mt][nt][1]+b1v)*scl);
                *(uint32_t*)&out[(size_t)(r+8)*C_ + c] =
                    pk2((acc[z][mt][nt][2]+b0v)*scl, (acc[z][mt][nt][3]+b1v)*scl);
            }
        }
    }
}

// ---------------- Kernel 4: V transpose -> g_vt[bh][d][tok] bf16 ----------
__global__ void vt_kernel()
{
    __shared__ bf16 t[32][33];
    int ttile = blockIdx.x, dtile = blockIdx.y, bh = blockIdx.z;
    int b = bh >> 2, h = bh & 3;
    int tx = threadIdx.x, ty = threadIdx.y;
    #pragma unroll
    for (int i = 0; i < 4; i++)
        t[ty+8*i][tx] = g_v[(size_t)(b*HW_ + ttile*32 + ty+8*i)*C_ + h*DH_ + dtile*32 + tx];
    __syncthreads();
    #pragma unroll
    for (int i = 0; i < 4; i++)
        g_vt[(size_t)bh*DH_*HW_ + (size_t)(dtile*32 + ty+8*i)*HW_ + ttile*32 + tx]
            = t[tx][ty+8*i];
}

// ---------------- Kernel 5: attention, FA2-style, P in registers ----------
#define SQst 72
__global__ __launch_bounds__(256,2) void attn_kernel()
{
    extern __shared__ bf16 smb[];
    bf16* sQ  = smb;               // [128][SQst]
    bf16* sK  = sQ  + 128*SQst;    // [64][SQst]  (key-major, d contig)
    bf16* sVt = sK  + 64*SQst;     // [64][SQst]  (d-major, key contig)
    int q0 = blockIdx.x*128;
    int bh = blockIdx.y, b = bh>>2, h = bh&3;
    size_t base = (size_t)b*HW_*C_ + (size_t)h*DH_;
    const bf16* vtb = g_vt + (size_t)bh*DH_*HW_;
    int tid = threadIdx.x, wid = tid>>5, lane = tid&31;
    int g = lane>>2, t = lane&3;

    // stage Q tile (128 x 64)
    #pragma unroll
    for (int i = 0; i < 4; i++) {
        int f = tid + i*256, row = f>>3, seg = (f&7)*8;
        *(uint4*)&sQ[row*SQst + seg] =
            *(const uint4*)&g_q[base + (size_t)(q0+row)*C_ + seg];
    }
    __syncthreads();
    // Q fragments -> registers (warp owns rows wid*16 .. +15)
    uint32_t aQ[4][4];
    {
        int r = wid*16 + g;
        #pragma unroll
        for (int k4 = 0; k4 < 4; k4++) {
            int kk = k4*16;
            aQ[k4][0] = lduint(&sQ[r*SQst + kk + 2*t]);
            aQ[k4][1] = lduint(&sQ[(r+8)*SQst + kk + 2*t]);
            aQ[k4][2] = lduint(&sQ[r*SQst + kk + 2*t + 8]);
            aQ[k4][3] = lduint(&sQ[(r+8)*SQst + kk + 2*t + 8]);
        }
    }

    float o[8][4];
    #pragma unroll
    for (int nt = 0; nt < 8; nt++)
        #pragma unroll
        for (int i = 0; i < 4; i++) o[nt][i] = 0.f;
    float lp0 = 0.f, lp1 = 0.f;

    // prefetch kt=0
    uint4 kreg[2], vreg[2];
    #pragma unroll
    for (int i = 0; i < 2; i++) {
        int f = tid + i*256, row = f>>3, seg = (f&7)*8;
        kreg[i] = *(const uint4*)&g_k[base + (size_t)row*C_ + seg];
        vreg[i] = *(const uint4*)&vtb[(size_t)row*HW_ + seg];
    }

    for (int kt = 0; kt < 16; kt++) {
        __syncthreads();
        #pragma unroll
        for (int i = 0; i < 2; i++) {
            int f = tid + i*256, row = f>>3, seg = (f&7)*8;
            *(uint4*)&sK[row*SQst + seg]  = kreg[i];
            *(uint4*)&sVt[row*SQst + seg] = vreg[i];
        }
        __syncthreads();
        if (kt < 15) {
            #pragma unroll
            for (int i = 0; i < 2; i++) {
                int f = tid + i*256, row = f>>3, seg = (f&7)*8;
                kreg[i] = *(const uint4*)&g_k[base + (size_t)((kt+1)*64+row)*C_ + seg];
                vreg[i] = *(const uint4*)&vtb[(size_t)row*HW_ + (kt+1)*64 + seg];
            }
        }
        // per 16-key slice: S (two n8 tiles) -> exp -> pack -> PV step
        #pragma unroll
        for (int s = 0; s < 4; s++) {
            float S0[4] = {0.f,0.f,0.f,0.f};
            float S1[4] = {0.f,0.f,0.f,0.f};
            int key0 = s*16 + g, key1 = key0 + 8;
            #pragma unroll
            for (int k4 = 0; k4 < 4; k4++) {
                int kk = k4*16;
                uint32_t b0 = lduint(&sK[key0*SQst + kk + 2*t]);
                uint32_t b1 = lduint(&sK[key0*SQst + kk + 2*t + 8]);
                mma16(S0, aQ[k4][0],aQ[k4][1],aQ[k4][2],aQ[k4][3], b0, b1);
                uint32_t c0 = lduint(&sK[key1*SQst + kk + 2*t]);
                uint32_t c1 = lduint(&sK[key1*SQst + kk + 2*t + 8]);
                mma16(S1, aQ[k4][0],aQ[k4][1],aQ[k4][2],aQ[k4][3], c0, c1);
            }
            float e00 = __expf(S0[0]), e01 = __expf(S0[1]);
            float e02 = __expf(S0[2]), e03 = __expf(S0[3]);
            float e10 = __expf(S1[0]), e11 = __expf(S1[1]);
            float e12 = __expf(S1[2]), e13 = __expf(S1[3]);
            lp0 += e00 + e01 + e10 + e11;
            lp1 += e02 + e03 + e12 + e13;
            uint32_t p0 = pk2(e00, e01);   // row g,   keys lo
            uint32_t p1 = pk2(e02, e03);   // row g+8, keys lo
            uint32_t p2 = pk2(e10, e11);   // row g,   keys hi
            uint32_t p3 = pk2(e12, e13);   // row g+8, keys hi
            int kkp = s*16;
            #pragma unroll
            for (int nt = 0; nt < 8; nt++) {
                int cn = nt*8 + g;
                uint32_t b0 = lduint(&sVt[cn*SQst + kkp + 2*t]);
                uint32_t b1 = lduint(&sVt[cn*SQst + kkp + 2*t + 8]);
                mma16(o[nt], p0, p1, p2, p3, b0, b1);
            }
        }
    }

    // row sums live in quads (lanes share g): reduce over t
    lp0 += __shfl_xor_sync(0xffffffffu, lp0, 1);
    lp0 += __shfl_xor_sync(0xffffffffu, lp0, 2);
    lp1 += __shfl_xor_sync(0xffffffffu, lp1, 1);
    lp1 += __shfl_xor_sync(0xffffffffu, lp1, 2);
    float inv0 = 1.f / lp0, inv1 = 1.f / lp1;

    int row = q0 + wid*16 + g;
    #pragma unroll
    for (int nt = 0; nt < 8; nt++) {
        int c = nt*8 + 2*t;
        *(uint32_t*)&g_h[base + (size_t)row*C_ + c] =
            pk2(o[nt][0]*inv0, o[nt][1]*inv0);
        *(uint32_t*)&g_h[base + (size_t)(row+8)*C_ + c] =
            pk2(o[nt][2]*inv1, o[nt][3]*inv1);
    }
}

// ---------------- Kernel 6: proj + bias + residual ----------------
__global__ __launch_bounds__(256) void proj_kernel(
    const float* __restrict__ bp, const float* __restrict__ x,
    float* __restrict__ out)
{
    extern __shared__ bf16 smb[];
    bf16* sA = smb;                 // [128][SAE]
    bf16* sB = sA + 128*SAE;        // [64][SBE]
    const bf16* WT = g_wt + (size_t)3*C_*C_;
    int d0 = blockIdx.x*64, m0 = blockIdx.y*128;
    int tid = threadIdx.x, wid = tid>>5, lane = tid&31;
    int g = lane>>2, t = lane&3;
    int m0w = (wid>>1)*32, n0w = (wid&1)*32;

    float acc[2][4][4];
    #pragma unroll
    for (int mt = 0; mt < 2; mt++)
        #pragma unroll
        for (int nt = 0; nt < 4; nt++)
            #pragma unroll
            for (int i = 0; i < 4; i++) acc[mt][nt][i] = 0.f;

    for (int kc = 0; kc < 8; kc++) {
        int k0 = kc*32;
        __syncthreads();
        #pragma unroll
        for (int i = 0; i < 2; i++) {
            int f = tid + i*256, row = f>>2, seg = (f&3)*8;
            *(uint4*)&sA[row*SAE + seg] =
                *(const uint4*)&g_h[(size_t)(m0+row)*C_ + k0 + seg];
        }
        {
            int n = tid>>2, seg = (tid&3)*8;
            *(uint4*)&sB[n*SBE + seg] =
                *(const uint4*)&WT[(size_t)(d0+n)*C_ + k0 + seg];
        }
        __syncthreads();
        #pragma unroll
        for (int s = 0; s < 2; s++) {
            int kk = s*16;
            uint32_t a[2][4];
            #pragma unroll
            for (int mt = 0; mt < 2; mt++) {
                int r = m0w + mt*16 + g;
                a[mt][0] = lduint(&sA[r*SAE + kk + 2*t]);
                a[mt][1] = lduint(&sA[(r+8)*SAE + kk + 2*t]);
                a[mt][2] = lduint(&sA[r*SAE + kk + 2*t + 8]);
                a[mt][3] = lduint(&sA[(r+8)*SAE + kk + 2*t + 8]);
            }
            #pragma unroll
            for (int nt = 0; nt < 4; nt++) {
                int cn = n0w + nt*8 + g;
                uint32_t b0 = lduint(&sB[cn*SBE + kk + 2*t]);
                uint32_t b1 = lduint(&sB[cn*SBE + kk + 2*t + 8]);
                #pragma unroll
                for (int mt = 0; mt < 2; mt++)
                    mma16(acc[mt][nt], a[mt][0],a[mt][1],a[mt][2],a[mt][3], b0, b1);
            }
        }
    }
    #pragma unroll
    for (int mt = 0; mt < 2; mt++) {
        #pragma unroll
        for (int rh = 0; rh < 2; rh++) {
            int r = m0 + m0w + mt*16 + g + rh*8;
            int bt = r >> 10, n = r & 1023;
            #pragma unroll
            for (int nt = 0; nt < 4; nt++) {
                int d = d0 + n0w + nt*8 + 2*t;
                size_t i0 = ((size_t)bt*C_ + d)*HW_ + n;
                size_t i1 = i0 + HW_;
                out[i0] = (acc[mt][nt][rh*2+0] + bp[d]   + x[i0]) * RS2_;
                out[i1] = (acc[mt][nt][rh*2+1] + bp[d+1] + x[i1]) * RS2_;
            }
        }
    }
}

// ---------------------------------------------------------------------------
extern "C" void kernel_launch(void* const* d_in, const int* in_sizes, int n_in,
                              void* d_out, int out_size)
{
    const float* x   = (const float*)d_in[0];
    const float* gns = (const float*)d_in[1];
    const float* gnb = (const float*)d_in[2];
    const float* Wq  = (const float*)d_in[3];
    const float* bq  = (const float*)d_in[4];
    const float* Wk  = (const float*)d_in[5];
    const float* bk  = (const float*)d_in[6];
    const float* Wv  = (const float*)d_in[7];
    const float* bv  = (const float*)d_in[8];
    const float* Wp  = (const float*)d_in[9];
    const float* bp  = (const float*)d_in[10];
    float* out = (float*)d_out;

    const int smem_qkv  = (128*SAE + 3*64*SBE) * 2;
    const int smem_attn = (128*SQst + 2*64*SQst) * 2;   // 36864
    const int smem_proj = (128*SAE + 64*SBE) * 2;

    gn_kernel  <<<B_*GROUPS_, 256>>>(x, gns, gnb);
    wt_kernel  <<<dim3(8,8,4), dim3(32,8)>>>(Wq, Wk, Wv, Wp);
    qkv_kernel <<<dim3(4, 128), 256, smem_qkv>>>(bq, bk, bv);
    vt_kernel  <<<dim3(32,2,64), dim3(32,8)>>>();
    attn_kernel<<<dim3(8, 64), 256, smem_attn>>>();
    proj_kernel<<<dim3(4, 128), 256, smem_proj>>>(bp, x, out);
}